// round 3
// baseline (speedup 1.0000x reference)
#include <cuda_runtime.h>

// SparseBiasDiagUnfolder — warp-per-window-row formulation.
//   adj: (B=2, N=2048, N=2048, F=16) fp32; starts 0,4,...,2040 (511);
//   out (B, 511, 56*16).
//
// Window row (b, s, ii) covers adj[b, 4s+ii, 4s+jj, :] for jj=0..7:
// 8*16 floats = 512 B CONTIGUOUS. One warp: lane l loads float4 (base + l)
// -> one fully coalesced 512B load. Output keeps the 7 off-diagonal
// positions (jj != ii), repacked contiguously: pos = ii*7 + jj - (jj>ii).
// Store: 28 active lanes write a contiguous 448 B run -> coalesced.

namespace {
constexpr int N        = 2048;
constexpr int NSTARTS  = 511;
constexpr int NROWS    = 2 * NSTARTS * 8;        // 8176 warps of work
constexpr int THREADS  = 256;
constexpr int BLOCKS   = NROWS / 8;              // 1022 (8 warps/block, exact)
}

__global__ void __launch_bounds__(THREADS)
sparse_diag_unfold_kernel(const float4* __restrict__ adj, float4* __restrict__ out)
{
    const int gt   = blockIdx.x * THREADS + threadIdx.x;
    const int w    = gt >> 5;          // warp id = (b*511 + s)*8 + ii
    const int lane = gt & 31;

    const int ii = w & 7;
    const int bs = w >> 3;             // b*511 + s
    const int s  = bs % NSTARTS;
    const int b  = bs / NSTARTS;

    // float4 base index of the row's 512B run:
    // ((b*N*N + 4s*(N+1) + ii*N) * 16 floats) / 4
    const long base = ((long)b * N * N
                     + (long)(4 * s) * (N + 1)
                     + (long)ii * N) * 4;

    const float4 val = adj[base + lane];   // fully coalesced 512B per warp

    const int jj = lane >> 2;
    const int v  = lane & 3;

    if (jj != ii) {
        const int pos = ii * 7 + jj - (jj > ii);      // 0..55 within window
        out[((long)bs * 56 + pos) * 4 + v] = val;     // contiguous 448B per warp
    }
}

extern "C" void kernel_launch(void* const* d_in, const int* in_sizes, int n_in,
                              void* d_out, int out_size)
{
    const float4* adj = (const float4*)d_in[0];
    float4* out = (float4*)d_out;
    sparse_diag_unfold_kernel<<<BLOCKS, THREADS>>>(adj, out);
}